// round 2
// baseline (speedup 1.0000x reference)
#include <cuda_runtime.h>

typedef unsigned long long ull;

#define B_    1024
#define N_    64
#define C_    16
#define M_    16
#define H_    512
#define T_    128
#define DIN_  80
#define ROWS  8
#define NTHR  256

// ---- packed f32x2 helpers (FFMA2 path: 2 MACs / instruction) ----
__device__ __forceinline__ ull fdup(float v){
    ull r; asm("mov.b64 %0, {%1, %1};" : "=l"(r) : "f"(v)); return r;
}
__device__ __forceinline__ void funpack(ull v, float &a, float &b){
    asm("mov.b64 {%0, %1}, %2;" : "=f"(a), "=f"(b) : "l"(v));
}
#define FFMA2(acc, a, b) asm("fma.rn.f32x2 %0, %1, %2, %0;" : "+l"(acc) : "l"(a), "l"(b))

__global__ void __launch_bounds__(NTHR, 1)
nsde_kernel(const float* __restrict__ y0,
            const float* __restrict__ controls,
            const float* __restrict__ noise,
            const float* __restrict__ W1mu, const float* __restrict__ b1mu,
            const float* __restrict__ W2mu, const float* __restrict__ b2mu,
            const float* __restrict__ W1sg, const float* __restrict__ b1sg,
            const float* __restrict__ W2sg, const float* __restrict__ b2sg,
            float* __restrict__ out)
{
    __shared__ float sx [DIN_][ROWS];   // x transposed: [i][row]
    __shared__ float shm[H_][ROWS];     // h_mu transposed
    __shared__ float shs[H_][ROWS];     // h_sg transposed
    __shared__ float sy [ROWS][N_];     // persistent state y
    __shared__ float sz [ROWS][M_];     // noise * sqrt(dt) this step
    __shared__ float sdp[4][N_][ROWS];  // partials (phase B, reused phase C)
    __shared__ float sdr[ROWS][N_];     // drift (incl. bias)

    const int t  = threadIdx.x;
    const int r0 = blockIdx.x * ROWS;

    // init y, write trajectory slice t=0
    for (int i = t; i < ROWS*N_; i += NTHR){
        int b = i >> 6, n = i & 63;
        float v = y0[(r0+b)*N_ + n];
        sy[b][n] = v;
        out[(size_t)(r0+b)*N_ + n] = v;
    }
    __syncthreads();

    for (int k = 0; k < T_-1; k++){
        // ---- build x (transposed) and pre-scaled noise ----
        for (int i = t; i < DIN_*ROWS; i += NTHR){
            int ii = i >> 3, b = i & 7;
            sx[ii][b] = (ii < N_) ? sy[b][ii] : controls[k*C_ + (ii - N_)];
        }
        for (int i = t; i < ROWS*M_; i += NTHR){
            int b = i >> 4, m = i & 15;
            sz[b][m] = noise[((size_t)k*B_ + r0 + b)*M_ + m] * 0.1f;
        }
        __syncthreads();

        // ---- Phase A: h_mu, h_sg (thread -> units 2t, 2t+1 of both) ----
        {
            const int j = 2*t;
            ull am[2][4], as2[2][4];
            #pragma unroll
            for (int u=0;u<2;u++)
                #pragma unroll
                for(int p=0;p<4;p++){ am[u][p]=0ull; as2[u][p]=0ull; }
            const float2* wmp = (const float2*)(W1mu + j);
            const float2* wsp = (const float2*)(W1sg + j);
            #pragma unroll 4
            for (int i=0;i<DIN_;i++){
                float2 wm = wmp[i*(H_/2)];
                float2 ws = wsp[i*(H_/2)];
                ull wm0 = fdup(wm.x), wm1 = fdup(wm.y);
                ull ws0 = fdup(ws.x), ws1 = fdup(ws.y);
                #pragma unroll
                for (int p=0;p<4;p++){
                    ull xv = *(const ull*)&sx[i][2*p];
                    FFMA2(am [0][p], xv, wm0);
                    FFMA2(am [1][p], xv, wm1);
                    FFMA2(as2[0][p], xv, ws0);
                    FFMA2(as2[1][p], xv, ws1);
                }
            }
            #pragma unroll
            for (int u=0;u<2;u++){
                float bm = b1mu[j+u], bs = b1sg[j+u];
                #pragma unroll
                for (int p=0;p<4;p++){
                    float a, b2;
                    funpack(am[u][p], a, b2);
                    shm[j+u][2*p]   = fmaxf(a + bm, 0.f);
                    shm[j+u][2*p+1] = fmaxf(b2 + bm, 0.f);
                    funpack(as2[u][p], a, b2);
                    shs[j+u][2*p]   = fmaxf(a + bs, 0.f);
                    shs[j+u][2*p+1] = fmaxf(b2 + bs, 0.f);
                }
            }
        }
        __syncthreads();

        // ---- Phase B: drift partials (64 cols x 4 K-segments) ----
        {
            const int col = t & 63;
            const int seg = t >> 6;
            ull acc[4] = {0ull,0ull,0ull,0ull};
            const float* w2 = W2mu + (size_t)(seg*128)*N_ + col;
            #pragma unroll 4
            for (int kk=0; kk<128; kk++){
                ull wd = fdup(w2[(size_t)kk*N_]);
                const int ki = seg*128 + kk;
                #pragma unroll
                for (int p=0;p<4;p++){
                    ull hv = *(const ull*)&shm[ki][2*p];
                    FFMA2(acc[p], hv, wd);
                }
            }
            #pragma unroll
            for (int p=0;p<4;p++){
                float a, b2; funpack(acc[p], a, b2);
                sdp[seg][col][2*p]   = a;
                sdp[seg][col][2*p+1] = b2;
            }
        }
        __syncthreads();
        for (int i = t; i < ROWS*N_; i += NTHR){
            int n = i & 63, b = i >> 6;
            sdr[b][n] = sdp[0][n][b] + sdp[1][n][b] + sdp[2][n][b] + sdp[3][n][b] + b2mu[n];
        }
        __syncthreads();

        // ---- Phase C: diffusion GEMM fused with dW contraction ----
        {
            const int j0 = 4*t;                 // 4 consecutive diffvec columns
            ull acc[4][4];
            #pragma unroll
            for (int c=0;c<4;c++)
                #pragma unroll
                for(int p=0;p<4;p++) acc[c][p]=0ull;
            const float4* wp = (const float4*)(W2sg + j0);
            #pragma unroll 2
            for (int kk=0; kk<H_; kk++){
                float4 w = wp[(size_t)kk*(1024/4)];
                ull wd0=fdup(w.x), wd1=fdup(w.y), wd2=fdup(w.z), wd3=fdup(w.w);
                ull h0 = *(const ull*)&shs[kk][0];
                ull h1 = *(const ull*)&shs[kk][2];
                ull h2 = *(const ull*)&shs[kk][4];
                ull h3 = *(const ull*)&shs[kk][6];
                FFMA2(acc[0][0],h0,wd0); FFMA2(acc[0][1],h1,wd0); FFMA2(acc[0][2],h2,wd0); FFMA2(acc[0][3],h3,wd0);
                FFMA2(acc[1][0],h0,wd1); FFMA2(acc[1][1],h1,wd1); FFMA2(acc[1][2],h2,wd1); FFMA2(acc[1][3],h3,wd1);
                FFMA2(acc[2][0],h0,wd2); FFMA2(acc[2][1],h1,wd2); FFMA2(acc[2][2],h2,wd2); FFMA2(acc[2][3],h3,wd2);
                FFMA2(acc[3][0],h0,wd3); FFMA2(acc[3][1],h1,wd3); FFMA2(acc[3][2],h2,wd3); FFMA2(acc[3][3],h3,wd3);
            }
            // epilogue: diff[n][m] = acc + bias; contribution = diff * (z*sqrt_dt)
            const int n  = t >> 2;
            const int g  = t & 3;
            const int mb = g * 4;
            float cont[ROWS];
            #pragma unroll
            for (int b=0;b<ROWS;b++) cont[b] = 0.f;
            #pragma unroll
            for (int c=0;c<4;c++){
                float bias = b2sg[j0 + c];
                #pragma unroll
                for (int p=0;p<4;p++){
                    float a, b2; funpack(acc[c][p], a, b2);
                    cont[2*p]   += (a  + bias) * sz[2*p  ][mb + c];
                    cont[2*p+1] += (b2 + bias) * sz[2*p+1][mb + c];
                }
            }
            #pragma unroll
            for (int b=0;b<ROWS;b++) sdp[g][n][b] = cont[b];
        }
        __syncthreads();

        // ---- y update + trajectory write ----
        for (int i = t; i < ROWS*N_; i += NTHR){
            int n = i & 63, b = i >> 6;
            float yn = sy[b][n] + 0.01f * sdr[b][n]
                     + sdp[0][n][b] + sdp[1][n][b] + sdp[2][n][b] + sdp[3][n][b];
            sy[b][n] = yn;
            out[((size_t)(k+1)*B_ + r0 + b)*N_ + n] = yn;
        }
        __syncthreads();
    }
}

extern "C" void kernel_launch(void* const* d_in, const int* in_sizes, int n_in,
                              void* d_out, int out_size)
{
    (void)in_sizes; (void)n_in; (void)out_size;
    nsde_kernel<<<B_/ROWS, NTHR>>>(
        (const float*)d_in[0],  // y0
        (const float*)d_in[1],  // controls
        (const float*)d_in[2],  // noise
        (const float*)d_in[3],  // W1_mu
        (const float*)d_in[4],  // b1_mu
        (const float*)d_in[5],  // W2_mu
        (const float*)d_in[6],  // b2_mu
        (const float*)d_in[7],  // W1_sg
        (const float*)d_in[8],  // b1_sg
        (const float*)d_in[9],  // W2_sg
        (const float*)d_in[10], // b2_sg
        (float*)d_out);
}

// round 3
// speedup vs baseline: 1.4910x; 1.4910x over previous
#include <cuda_runtime.h>

typedef unsigned long long ull;

#define B_    1024
#define N_    64
#define C_    16
#define M_    16
#define H_    512
#define T_    128
#define DIN_  80
#define ROWS  8
#define NTHR  512

// ---- packed f32x2 helpers (FFMA2 path: 2 MACs / instruction) ----
__device__ __forceinline__ ull fdup(float v){
    ull r; asm("mov.b64 %0, {%1, %1};" : "=l"(r) : "f"(v)); return r;
}
__device__ __forceinline__ void funpack(ull v, float &a, float &b){
    asm("mov.b64 {%0, %1}, %2;" : "=f"(a), "=f"(b) : "l"(v));
}
#define FFMA2(acc, a, b) asm("fma.rn.f32x2 %0, %1, %2, %0;" : "+l"(acc) : "l"(a), "l"(b))

__global__ void __launch_bounds__(NTHR, 1)
nsde_kernel(const float* __restrict__ y0,
            const float* __restrict__ controls,
            const float* __restrict__ noise,
            const float* __restrict__ W1mu, const float* __restrict__ b1mu,
            const float* __restrict__ W2mu, const float* __restrict__ b2mu,
            const float* __restrict__ W1sg, const float* __restrict__ b1sg,
            const float* __restrict__ W2sg, const float* __restrict__ b2sg,
            float* __restrict__ out)
{
    __shared__ float sx [DIN_][ROWS];   // x transposed: [i][row]
    __shared__ float shm[H_][ROWS];     // h_mu transposed
    __shared__ float shs[H_][ROWS];     // h_sg transposed
    __shared__ float sy [ROWS][N_];     // persistent state y
    __shared__ float sz [ROWS][M_];     // noise * sqrt(dt) this step
    __shared__ float sdp[8][N_][ROWS];  // partials (phase B, reused phase C)
    __shared__ float sdr[ROWS][N_];     // drift (incl. bias)

    const int t  = threadIdx.x;
    const int r0 = blockIdx.x * ROWS;

    // init y, write trajectory slice t=0  (ROWS*N_ = 512 = NTHR)
    {
        int b = t >> 6, n = t & 63;
        float v = y0[(r0+b)*N_ + n];
        sy[b][n] = v;
        out[(size_t)(r0+b)*N_ + n] = v;
    }
    __syncthreads();

    for (int k = 0; k < T_-1; k++){
        // ---- build x (transposed) and pre-scaled noise ----
        for (int i = t; i < DIN_*ROWS; i += NTHR){
            int ii = i >> 3, b = i & 7;
            sx[ii][b] = (ii < N_) ? sy[b][ii] : controls[k*C_ + (ii - N_)];
        }
        if (t < ROWS*M_){
            int b = t >> 4, m = t & 15;
            sz[b][m] = noise[((size_t)k*B_ + r0 + b)*M_ + m] * 0.1f;
        }
        __syncthreads();

        // ---- Phase A: h_mu[j], h_sg[j] for j = t (one unit each) ----
        {
            const int j = t;
            ull am[4], as2[4];
            #pragma unroll
            for (int p=0;p<4;p++){ am[p]=0ull; as2[p]=0ull; }
            const float* wm = W1mu + j;
            const float* ws = W1sg + j;
            #pragma unroll 4
            for (int i=0;i<DIN_;i++){
                ull wmd = fdup(wm[(size_t)i*H_]);
                ull wsd = fdup(ws[(size_t)i*H_]);
                #pragma unroll
                for (int p=0;p<4;p++){
                    ull xv = *(const ull*)&sx[i][2*p];
                    FFMA2(am [p], xv, wmd);
                    FFMA2(as2[p], xv, wsd);
                }
            }
            float bm = b1mu[j], bs = b1sg[j];
            #pragma unroll
            for (int p=0;p<4;p++){
                float a, b2;
                funpack(am[p], a, b2);
                shm[j][2*p]   = fmaxf(a  + bm, 0.f);
                shm[j][2*p+1] = fmaxf(b2 + bm, 0.f);
                funpack(as2[p], a, b2);
                shs[j][2*p]   = fmaxf(a  + bs, 0.f);
                shs[j][2*p+1] = fmaxf(b2 + bs, 0.f);
            }
        }
        __syncthreads();

        // ---- Phase B: drift partials (64 cols x 8 K-segments of 64) ----
        {
            const int col = t & 63;
            const int seg = t >> 6;
            ull acc[4] = {0ull,0ull,0ull,0ull};
            const float* w2 = W2mu + (size_t)(seg*64)*N_ + col;
            #pragma unroll 8
            for (int kk=0; kk<64; kk++){
                ull wd = fdup(w2[(size_t)kk*N_]);
                const int ki = seg*64 + kk;
                #pragma unroll
                for (int p=0;p<4;p++){
                    ull hv = *(const ull*)&shm[ki][2*p];
                    FFMA2(acc[p], hv, wd);
                }
            }
            #pragma unroll
            for (int p=0;p<4;p++){
                float a, b2; funpack(acc[p], a, b2);
                sdp[seg][col][2*p]   = a;
                sdp[seg][col][2*p+1] = b2;
            }
        }
        __syncthreads();
        {   // reduce drift partials (512 threads = 8 rows x 64 cols)
            int n = t & 63, b = t >> 6;
            float s = b2mu[n];
            #pragma unroll
            for (int g=0; g<8; g++) s += sdp[g][n][b];
            sdr[b][n] = s;
        }
        __syncthreads();

        // ---- Phase C: diffusion GEMM fused with dW contraction ----
        {
            const int j0 = 2*t;                 // 2 consecutive diffvec columns
            ull acc[2][4];
            #pragma unroll
            for (int c=0;c<2;c++)
                #pragma unroll
                for(int p=0;p<4;p++) acc[c][p]=0ull;
            const float2* wp = (const float2*)(W2sg + j0);
            #pragma unroll 4
            for (int kk=0; kk<H_; kk++){
                float2 w = wp[(size_t)kk*(1024/2)];
                ull wd0=fdup(w.x), wd1=fdup(w.y);
                ull h0 = *(const ull*)&shs[kk][0];
                ull h1 = *(const ull*)&shs[kk][2];
                ull h2 = *(const ull*)&shs[kk][4];
                ull h3 = *(const ull*)&shs[kk][6];
                FFMA2(acc[0][0],h0,wd0); FFMA2(acc[0][1],h1,wd0);
                FFMA2(acc[0][2],h2,wd0); FFMA2(acc[0][3],h3,wd0);
                FFMA2(acc[1][0],h0,wd1); FFMA2(acc[1][1],h1,wd1);
                FFMA2(acc[1][2],h2,wd1); FFMA2(acc[1][3],h3,wd1);
            }
            // epilogue: columns j0,j0+1 -> (n = t>>3, m = 2g, 2g+1), g = t&7
            const int n  = t >> 3;
            const int g  = t & 7;
            float bias0 = b2sg[j0], bias1 = b2sg[j0+1];
            float cont[ROWS];
            #pragma unroll
            for (int p=0;p<4;p++){
                float a0, b0, a1, b1v;
                funpack(acc[0][p], a0, b0);
                funpack(acc[1][p], a1, b1v);
                cont[2*p]   = (a0  + bias0) * sz[2*p  ][2*g]
                            + (a1  + bias1) * sz[2*p  ][2*g+1];
                cont[2*p+1] = (b0  + bias0) * sz[2*p+1][2*g]
                            + (b1v + bias1) * sz[2*p+1][2*g+1];
            }
            #pragma unroll
            for (int b=0;b<ROWS;b++) sdp[g][n][b] = cont[b];
        }
        __syncthreads();

        // ---- y update + trajectory write (512 threads = 8 rows x 64 cols) ----
        {
            int n = t & 63, b = t >> 6;
            float yn = sy[b][n] + 0.01f * sdr[b][n];
            #pragma unroll
            for (int g=0; g<8; g++) yn += sdp[g][n][b];
            sy[b][n] = yn;
            out[((size_t)(k+1)*B_ + r0 + b)*N_ + n] = yn;
        }
        __syncthreads();
    }
}

extern "C" void kernel_launch(void* const* d_in, const int* in_sizes, int n_in,
                              void* d_out, int out_size)
{
    (void)in_sizes; (void)n_in; (void)out_size;
    nsde_kernel<<<B_/ROWS, NTHR>>>(
        (const float*)d_in[0],  // y0
        (const float*)d_in[1],  // controls
        (const float*)d_in[2],  // noise
        (const float*)d_in[3],  // W1_mu
        (const float*)d_in[4],  // b1_mu
        (const float*)d_in[5],  // W2_mu
        (const float*)d_in[6],  // b2_mu
        (const float*)d_in[7],  // W1_sg
        (const float*)d_in[8],  // b1_sg
        (const float*)d_in[9],  // W2_sg
        (const float*)d_in[10], // b2_sg
        (float*)d_out);
}